// round 4
// baseline (speedup 1.0000x reference)
#include <cuda_runtime.h>

#define B_     8
#define NA_    9
#define NH_    64
#define NW_    64
#define NG_    32
#define NC_    80
#define NANCH  (NA_*NH_*NW_)        // 36864
#define TPB    256
#define BPI    (NANCH/TPB)          // 144 blocks per image
#define NBLK   (B_*BPI)             // 1152

// per-block partials (deterministic reduction, no atomics on floats)
__device__ float g_cls [NBLK];
__device__ float g_xywh[NBLK];
__device__ float g_npos[NBLK];
__device__ unsigned int g_count = 0;   // last-block-done counter (reset each run)

// anchor w/h: base=32, scales {1, 1.2599, 1.5874}, ratios {(1,1),(1.4,0.7),(0.7,1.4)}
__constant__ float c_aw[9] = {
    (float)(32.0*1.0),        (float)(32.0*1.0*1.4),        (float)(32.0*1.0*0.7),
    (float)(32.0*1.2599),     (float)(32.0*1.2599*1.4),     (float)(32.0*1.2599*0.7),
    (float)(32.0*1.5874),     (float)(32.0*1.5874*1.4),     (float)(32.0*1.5874*0.7)
};
__constant__ float c_ah[9] = {
    (float)(32.0*1.0),        (float)(32.0*1.0*0.7),        (float)(32.0*1.0*1.4),
    (float)(32.0*1.2599),     (float)(32.0*1.2599*0.7),     (float)(32.0*1.2599*1.4),
    (float)(32.0*1.5874),     (float)(32.0*1.5874*0.7),     (float)(32.0*1.5874*1.4)
};

__device__ __forceinline__ float ex2f(float x) {
    float y; asm("ex2.approx.f32 %0, %1;" : "=f"(y) : "f"(x)); return y;
}
__device__ __forceinline__ float lg2f(float x) {
    float y; asm("lg2.approx.f32 %0, %1;" : "=f"(y) : "f"(x)); return y;
}

__global__ void __launch_bounds__(TPB, 8)
retina_fused(const float* __restrict__ t_xywh,
             const float* __restrict__ logits,
             const float* __restrict__ gtb,
             const int*   __restrict__ gtc,
             float* __restrict__ out)
{
    __shared__ float4 s_tlbr[NG_];   // tlx,tly,brx,bry
    __shared__ float4 s_box [NG_];   // cx,cy,w,h
    __shared__ float  s_area[NG_];
    __shared__ int    s_cat [NG_];
    __shared__ float  s_penf[TPB];   // per-anchor penalty flag (0/1)
    __shared__ float  s_red[3][8];
    __shared__ float  s_fin[16];
    __shared__ unsigned int s_last;

    const int bid = blockIdx.x;
    const int b   = bid / BPI;
    const int blk = bid % BPI;
    const int tid = threadIdx.x;

    if (tid < NG_) {
        float4 g = ((const float4*)gtb)[b*NG_ + tid];
        float hw = 0.5f*g.z, hh = 0.5f*g.w;
        s_tlbr[tid] = make_float4(g.x - hw, g.y - hh, g.x + hw, g.y + hh);
        s_box [tid] = g;
        s_area[tid] = g.z * g.w;
        s_cat [tid] = gtc[b*NG_ + tid];
    }
    __syncthreads();

    // ---- phase 1: per-anchor IoU argmax, pos/neg, regression loss ----
    const int n = blk*TPB + tid;        // anchor index within image: a*4096 + h*64 + w
    const int a = n >> 12;
    const int h = (n >> 6) & 63;
    const int w = n & 63;

    const float aw = c_aw[a], ah = c_ah[a];
    const float acx = ((float)w + 0.5f) * 8.0f;
    const float acy = ((float)h + 0.5f) * 8.0f;
    const float atlx = acx - 0.5f*aw, atly = acy - 0.5f*ah;
    const float abrx = acx + 0.5f*aw, abry = acy + 0.5f*ah;
    const float areaA = aw * ah;

    // best IoU tracked as (I, U) pair: cross-multiplied compare, no division
    float bI = 0.0f, bU = 1.0f;
    int   bG = 0;
    #pragma unroll 4
    for (int g = 0; g < NG_; ++g) {
        float4 t = s_tlbr[g];
        float ox = fminf(abrx, t.z) - fmaxf(atlx, t.x);
        float oy = fminf(abry, t.w) - fmaxf(atly, t.y);
        ox = fmaxf(ox, 0.0f);
        oy = fmaxf(oy, 0.0f);
        float I = ox * oy;
        float U = (areaA - I) + s_area[g];
        if (I * bU > bI * U) { bI = I; bU = U; bG = g; }
    }

    const bool pos = bI > 0.5f * bU;
    const bool neg = bI < 0.4f * bU;

    float l_xywh = 0.0f;
    float sub    = 0.0f;     // one-hot -x[tc] term (pos anchors only)
    if (pos) {
        float4 g = s_box[bG];
        float tx = (g.x - acx) / aw;
        float ty = (g.y - acy) / ah;
        float tw = __logf(g.z / aw + 1e-8f);
        float th = __logf(g.w / ah + 1e-8f);
        float4 t = ((const float4*)t_xywh)[ (size_t)((b*NA_ + a) << 12) + (h << 6) + w ];
        float dx = t.x - tx, dy = t.y - ty, dw = t.z - tw, dh = t.w - th;
        l_xywh = dx*dx + dy*dy + dw*dw + dh*dh;
        sub = logits[(size_t)(b*NANCH + n)*NC_ + s_cat[bG]];
    }

    s_penf[tid] = (pos | neg) ? 1.0f : 0.0f;
    __syncthreads();

    // ---- phase 2: block-cooperative, coalesced BCE over 256 anchors x 80 classes ----
    // softplus(x) = max(x,0) + log1p(exp(-|x|)); the 4 factors (1+y_i) of one
    // float4 share an anchor, so the penalty mask is applied ONCE per float4:
    // q = prod(1+y_i) unconditionally, then p = pen ? p*q : p. 16 factors per
    // lg2 (p in [1, 2^16], safe in f32).
    const float4* lp = (const float4*)logits + (size_t)(b*NANCH + blk*TPB)*(NC_/4);
    float acc_r = -sub, acc_l = 0.0f, p = 1.0f;
    #pragma unroll
    for (int k = 0; k < 20; ++k) {        // 20 * 256 float4 = 256 anchors * 80
        const int idx4   = tid + k*TPB;   // 0..5119
        const int anchor = idx4 / (NC_/4);
        const float pen  = s_penf[anchor];
        const bool  pb   = pen > 0.5f;
        float4 v = lp[idx4];
        float y0 = ex2f(-1.4426950408889634f * fabsf(v.x));
        float y1 = ex2f(-1.4426950408889634f * fabsf(v.y));
        float y2 = ex2f(-1.4426950408889634f * fabsf(v.z));
        float y3 = ex2f(-1.4426950408889634f * fabsf(v.w));
        float q = 1.0f + y0;
        q = __fmaf_rn(q, y1, q);
        q = __fmaf_rn(q, y2, q);
        q = __fmaf_rn(q, y3, q);
        float pq = p * q;
        p = pb ? pq : p;
        float m = (fmaxf(v.x, 0.0f) + fmaxf(v.y, 0.0f))
                + (fmaxf(v.z, 0.0f) + fmaxf(v.w, 0.0f));
        acc_r = __fmaf_rn(pen, m, acc_r);
        if ((k & 3) == 3) { acc_l += lg2f(p); p = 1.0f; }
    }
    float acc_cls = acc_r + 0.6931471805599453f * acc_l;

    // ---- block reduction of (cls, xywh, npos) ----
    float v0 = acc_cls, v1 = l_xywh, v2 = pos ? 1.0f : 0.0f;
    #pragma unroll
    for (int o = 16; o; o >>= 1) {
        v0 += __shfl_down_sync(0xFFFFFFFFu, v0, o);
        v1 += __shfl_down_sync(0xFFFFFFFFu, v1, o);
        v2 += __shfl_down_sync(0xFFFFFFFFu, v2, o);
    }
    const int lane = tid & 31, wrp = tid >> 5;
    if (lane == 0) { s_red[0][wrp] = v0; s_red[1][wrp] = v1; s_red[2][wrp] = v2; }
    __syncthreads();
    if (wrp == 0 && lane < 8) {
        v0 = s_red[0][lane]; v1 = s_red[1][lane]; v2 = s_red[2][lane];
        #pragma unroll
        for (int o = 4; o; o >>= 1) {
            v0 += __shfl_down_sync(0x000000FFu, v0, o);
            v1 += __shfl_down_sync(0x000000FFu, v1, o);
            v2 += __shfl_down_sync(0x000000FFu, v2, o);
        }
        if (lane == 0) { g_cls[bid] = v0; g_xywh[bid] = v1; g_npos[bid] = v2; }
    }
    __syncthreads();

    // ---- last-block-done: final deterministic reduction, no 2nd launch ----
    if (tid == 0) {
        __threadfence();
        s_last = (atomicAdd(&g_count, 1u) == NBLK - 1u);
    }
    __syncthreads();
    if (!s_last) return;
    __threadfence();

    // global xywh sum over all 1152 partials (fixed order -> deterministic)
    float sx = 0.0f;
    for (int i = tid; i < NBLK; i += TPB) sx += __ldcg(&g_xywh[i]);
    #pragma unroll
    for (int o = 16; o; o >>= 1) sx += __shfl_down_sync(0xFFFFFFFFu, sx, o);
    if (lane == 0) s_fin[wrp] = sx;

    // per-image cls sum / (npos+1): warp `wrp` handles image `wrp`
    float sc = 0.0f, sp = 0.0f;
    for (int i = lane; i < BPI; i += 32) {
        sc += __ldcg(&g_cls [wrp*BPI + i]);
        sp += __ldcg(&g_npos[wrp*BPI + i]);
    }
    #pragma unroll
    for (int o = 16; o; o >>= 1) {
        sc += __shfl_down_sync(0xFFFFFFFFu, sc, o);
        sp += __shfl_down_sync(0xFFFFFFFFu, sp, o);
    }
    if (lane == 0) s_fin[8 + wrp] = sc / (sp + 1.0f);
    __syncthreads();

    if (tid == 0) {
        float tot = 0.0f;
        #pragma unroll
        for (int i = 0; i < 16; ++i) tot += s_fin[i];
        out[0] = tot * (1.0f / (float)B_);
        g_count = 0;   // reset for next graph replay
    }
}

extern "C" void kernel_launch(void* const* d_in, const int* in_sizes, int n_in,
                              void* d_out, int out_size)
{
    const float* t_xywh = (const float*)d_in[0];
    const float* logits = (const float*)d_in[1];
    const float* gtb    = (const float*)d_in[2];
    const int*   gtc    = (const int*)  d_in[3];
    (void)in_sizes; (void)n_in; (void)out_size;

    retina_fused<<<NBLK, TPB>>>(t_xywh, logits, gtb, gtc, (float*)d_out);
}

// round 5
// speedup vs baseline: 1.0357x; 1.0357x over previous
#include <cuda_runtime.h>

#define B_     8
#define NA_    9
#define NH_    64
#define NW_    64
#define NG_    32
#define NC_    80
#define NANCH  (NA_*NH_*NW_)        // 36864
#define TPB    256
#define BPI    (NANCH/TPB)          // 144 blocks per image
#define NBLK   (B_*BPI)             // 1152
#define NITER  20                   // float4 loop iterations per thread
#define STAGES 4

// per-block partials (deterministic reduction, no atomics on floats)
__device__ float g_cls [NBLK];
__device__ float g_xywh[NBLK];
__device__ float g_npos[NBLK];
__device__ unsigned int g_count = 0;   // last-block-done counter (reset each run)

// anchor w/h: base=32, scales {1, 1.2599, 1.5874}, ratios {(1,1),(1.4,0.7),(0.7,1.4)}
__constant__ float c_aw[9] = {
    (float)(32.0*1.0),        (float)(32.0*1.0*1.4),        (float)(32.0*1.0*0.7),
    (float)(32.0*1.2599),     (float)(32.0*1.2599*1.4),     (float)(32.0*1.2599*0.7),
    (float)(32.0*1.5874),     (float)(32.0*1.5874*1.4),     (float)(32.0*1.5874*0.7)
};
__constant__ float c_ah[9] = {
    (float)(32.0*1.0),        (float)(32.0*1.0*0.7),        (float)(32.0*1.0*1.4),
    (float)(32.0*1.2599),     (float)(32.0*1.2599*0.7),     (float)(32.0*1.2599*1.4),
    (float)(32.0*1.5874),     (float)(32.0*1.5874*0.7),     (float)(32.0*1.5874*1.4)
};

__device__ __forceinline__ float ex2f(float x) {
    float y; asm("ex2.approx.f32 %0, %1;" : "=f"(y) : "f"(x)); return y;
}
__device__ __forceinline__ float lg2f(float x) {
    float y; asm("lg2.approx.f32 %0, %1;" : "=f"(y) : "f"(x)); return y;
}
__device__ __forceinline__ void cp16(unsigned int smem_addr, const void* gptr) {
    asm volatile("cp.async.cg.shared.global [%0], [%1], 16;"
                 :: "r"(smem_addr), "l"(gptr));
}
__device__ __forceinline__ void cp_commit() {
    asm volatile("cp.async.commit_group;");
}
template<int N> __device__ __forceinline__ void cp_wait() {
    asm volatile("cp.async.wait_group %0;" :: "n"(N));
}

__global__ void __launch_bounds__(TPB)
retina_fused(const float* __restrict__ t_xywh,
             const float* __restrict__ logits,
             const float* __restrict__ gtb,
             const int*   __restrict__ gtc,
             float* __restrict__ out)
{
    __shared__ float4 s_stage[STAGES][TPB];   // 16KB cp.async ring (thread-private slots)
    __shared__ float4 s_tlbr[NG_];   // tlx,tly,brx,bry
    __shared__ float4 s_box [NG_];   // cx,cy,w,h
    __shared__ float  s_area[NG_];
    __shared__ int    s_cat [NG_];
    __shared__ float  s_penf[TPB];   // per-anchor penalty flag (0/1)
    __shared__ float  s_red[3][8];
    __shared__ float  s_fin[16];
    __shared__ unsigned int s_last;

    const int bid = blockIdx.x;
    const int b   = bid / BPI;
    const int blk = bid % BPI;
    const int tid = threadIdx.x;

    if (tid < NG_) {
        float4 g = ((const float4*)gtb)[b*NG_ + tid];
        float hw = 0.5f*g.z, hh = 0.5f*g.w;
        s_tlbr[tid] = make_float4(g.x - hw, g.y - hh, g.x + hw, g.y + hh);
        s_box [tid] = g;
        s_area[tid] = g.z * g.w;
        s_cat [tid] = gtc[b*NG_ + tid];
    }

    // ---- kick off logits prefetch pipeline (independent of phase 1) ----
    const float4* lp = (const float4*)logits + (size_t)(b*NANCH + blk*TPB)*(NC_/4);
    unsigned int my_slot[STAGES];
    #pragma unroll
    for (int s = 0; s < STAGES; ++s)
        my_slot[s] = (unsigned int)__cvta_generic_to_shared(&s_stage[s][tid]);
    #pragma unroll
    for (int s = 0; s < STAGES; ++s) {
        cp16(my_slot[s], lp + (tid + s*TPB));
        cp_commit();
    }

    __syncthreads();   // GT tables ready

    // ---- phase 1: per-anchor IoU argmax, pos/neg, regression loss ----
    const int n = blk*TPB + tid;        // anchor index within image: a*4096 + h*64 + w
    const int a = n >> 12;
    const int h = (n >> 6) & 63;
    const int w = n & 63;

    const float aw = c_aw[a], ah = c_ah[a];
    const float acx = ((float)w + 0.5f) * 8.0f;
    const float acy = ((float)h + 0.5f) * 8.0f;
    const float atlx = acx - 0.5f*aw, atly = acy - 0.5f*ah;
    const float abrx = acx + 0.5f*aw, abry = acy + 0.5f*ah;
    const float areaA = aw * ah;

    // best IoU tracked as (I, U) pair: cross-multiplied compare, no division
    float bI = 0.0f, bU = 1.0f;
    int   bG = 0;
    #pragma unroll 4
    for (int g = 0; g < NG_; ++g) {
        float4 t = s_tlbr[g];
        float ox = fminf(abrx, t.z) - fmaxf(atlx, t.x);
        float oy = fminf(abry, t.w) - fmaxf(atly, t.y);
        ox = fmaxf(ox, 0.0f);
        oy = fmaxf(oy, 0.0f);
        float I = ox * oy;
        float U = (areaA - I) + s_area[g];
        if (I * bU > bI * U) { bI = I; bU = U; bG = g; }
    }

    const bool pos = bI > 0.5f * bU;
    const bool neg = bI < 0.4f * bU;

    float l_xywh = 0.0f;
    float sub    = 0.0f;     // one-hot -x[tc] term (pos anchors only)
    if (pos) {
        float4 g = s_box[bG];
        float tx = (g.x - acx) / aw;
        float ty = (g.y - acy) / ah;
        float tw = __logf(g.z / aw + 1e-8f);
        float th = __logf(g.w / ah + 1e-8f);
        float4 t = ((const float4*)t_xywh)[ (size_t)((b*NA_ + a) << 12) + (h << 6) + w ];
        float dx = t.x - tx, dy = t.y - ty, dw = t.z - tw, dh = t.w - th;
        l_xywh = dx*dx + dy*dy + dw*dw + dh*dh;
        sub = logits[(size_t)(b*NANCH + n)*NC_ + s_cat[bG]];
    }

    s_penf[tid] = (pos | neg) ? 1.0f : 0.0f;
    __syncthreads();

    // ---- phase 2: pipelined, coalesced BCE over 256 anchors x 80 classes ----
    // Thread t at iter k consumes exactly the float4 it prefetched (slot k%STAGES):
    // producer == consumer -> per-thread cp.async.wait_group only, NO barriers.
    // softplus(x) = max(x,0) + log1p(exp(-|x|)); the 4 factors (1+y_i) of one
    // float4 share an anchor, so the mask is applied once per float4; 16 factors
    // per lg2 (product in [1, 2^16], safe in f32).
    float acc_r = -sub, acc_l = 0.0f, p = 1.0f;
    #pragma unroll
    for (int k = 0; k < NITER; ++k) {
        cp_wait<STAGES-1>();                 // stage k landed (per-thread)
        float4 v = s_stage[k % STAGES][tid];
        if (k + STAGES < NITER) {            // refill the slot we just freed
            cp16(my_slot[k % STAGES], lp + (tid + (k+STAGES)*TPB));
        }
        cp_commit();                         // keep group count in lockstep

        const int anchor = (tid + k*TPB) / (NC_/4);
        const float pen  = s_penf[anchor];
        const bool  pb   = pen > 0.5f;
        float y0 = ex2f(-1.4426950408889634f * fabsf(v.x));
        float y1 = ex2f(-1.4426950408889634f * fabsf(v.y));
        float y2 = ex2f(-1.4426950408889634f * fabsf(v.z));
        float y3 = ex2f(-1.4426950408889634f * fabsf(v.w));
        float q = 1.0f + y0;
        q = __fmaf_rn(q, y1, q);
        q = __fmaf_rn(q, y2, q);
        q = __fmaf_rn(q, y3, q);
        float pq = p * q;
        p = pb ? pq : p;
        float m = (fmaxf(v.x, 0.0f) + fmaxf(v.y, 0.0f))
                + (fmaxf(v.z, 0.0f) + fmaxf(v.w, 0.0f));
        acc_r = __fmaf_rn(pen, m, acc_r);
        if ((k & 3) == 3) { acc_l += lg2f(p); p = 1.0f; }
    }
    float acc_cls = acc_r + 0.6931471805599453f * acc_l;

    // ---- block reduction of (cls, xywh, npos) ----
    float v0 = acc_cls, v1 = l_xywh, v2 = pos ? 1.0f : 0.0f;
    #pragma unroll
    for (int o = 16; o; o >>= 1) {
        v0 += __shfl_down_sync(0xFFFFFFFFu, v0, o);
        v1 += __shfl_down_sync(0xFFFFFFFFu, v1, o);
        v2 += __shfl_down_sync(0xFFFFFFFFu, v2, o);
    }
    const int lane = tid & 31, wrp = tid >> 5;
    if (lane == 0) { s_red[0][wrp] = v0; s_red[1][wrp] = v1; s_red[2][wrp] = v2; }
    __syncthreads();
    if (wrp == 0 && lane < 8) {
        v0 = s_red[0][lane]; v1 = s_red[1][lane]; v2 = s_red[2][lane];
        #pragma unroll
        for (int o = 4; o; o >>= 1) {
            v0 += __shfl_down_sync(0x000000FFu, v0, o);
            v1 += __shfl_down_sync(0x000000FFu, v1, o);
            v2 += __shfl_down_sync(0x000000FFu, v2, o);
        }
        if (lane == 0) { g_cls[bid] = v0; g_xywh[bid] = v1; g_npos[bid] = v2; }
    }
    __syncthreads();

    // ---- last-block-done: final deterministic reduction, no 2nd launch ----
    if (tid == 0) {
        __threadfence();
        s_last = (atomicAdd(&g_count, 1u) == NBLK - 1u);
    }
    __syncthreads();
    if (!s_last) return;
    __threadfence();

    // global xywh sum over all 1152 partials (fixed order -> deterministic)
    float sx = 0.0f;
    for (int i = tid; i < NBLK; i += TPB) sx += __ldcg(&g_xywh[i]);
    #pragma unroll
    for (int o = 16; o; o >>= 1) sx += __shfl_down_sync(0xFFFFFFFFu, sx, o);
    if (lane == 0) s_fin[wrp] = sx;

    // per-image cls sum / (npos+1): warp `wrp` handles image `wrp`
    float sc = 0.0f, sp = 0.0f;
    for (int i = lane; i < BPI; i += 32) {
        sc += __ldcg(&g_cls [wrp*BPI + i]);
        sp += __ldcg(&g_npos[wrp*BPI + i]);
    }
    #pragma unroll
    for (int o = 16; o; o >>= 1) {
        sc += __shfl_down_sync(0xFFFFFFFFu, sc, o);
        sp += __shfl_down_sync(0xFFFFFFFFu, sp, o);
    }
    if (lane == 0) s_fin[8 + wrp] = sc / (sp + 1.0f);
    __syncthreads();

    if (tid == 0) {
        float tot = 0.0f;
        #pragma unroll
        for (int i = 0; i < 16; ++i) tot += s_fin[i];
        out[0] = tot * (1.0f / (float)B_);
        g_count = 0;   // reset for next graph replay
    }
}

extern "C" void kernel_launch(void* const* d_in, const int* in_sizes, int n_in,
                              void* d_out, int out_size)
{
    const float* t_xywh = (const float*)d_in[0];
    const float* logits = (const float*)d_in[1];
    const float* gtb    = (const float*)d_in[2];
    const int*   gtc    = (const int*)  d_in[3];
    (void)in_sizes; (void)n_in; (void)out_size;

    retina_fused<<<NBLK, TPB>>>(t_xywh, logits, gtb, gtc, (float*)d_out);
}

// round 6
// speedup vs baseline: 1.1987x; 1.1574x over previous
#include <cuda_runtime.h>

#define B_     8
#define NA_    9
#define NH_    64
#define NW_    64
#define NG_    32
#define NC_    80
#define NANCH  (NA_*NH_*NW_)        // 36864
#define TPB    512
#define BPI    (NANCH/TPB)          // 72 blocks per image
#define NBLK   (B_*BPI)             // 576
#define NITER  20                   // float4 per anchor (80 classes)

// per-block partials (deterministic reduction, no float atomics)
__device__ float g_cls [NBLK];
__device__ float g_xywh[NBLK];
__device__ float g_npos[NBLK];
__device__ unsigned int g_count = 0;   // last-block-done counter (reset each run)

// anchor w/h: base=32, scales {1, 1.2599, 1.5874}, ratios {(1,1),(1.4,0.7),(0.7,1.4)}
__constant__ float c_aw[9] = {
    (float)(32.0*1.0),        (float)(32.0*1.0*1.4),        (float)(32.0*1.0*0.7),
    (float)(32.0*1.2599),     (float)(32.0*1.2599*1.4),     (float)(32.0*1.2599*0.7),
    (float)(32.0*1.5874),     (float)(32.0*1.5874*1.4),     (float)(32.0*1.5874*0.7)
};
__constant__ float c_ah[9] = {
    (float)(32.0*1.0),        (float)(32.0*1.0*0.7),        (float)(32.0*1.0*1.4),
    (float)(32.0*1.2599),     (float)(32.0*1.2599*0.7),     (float)(32.0*1.2599*1.4),
    (float)(32.0*1.5874),     (float)(32.0*1.5874*0.7),     (float)(32.0*1.5874*1.4)
};

__device__ __forceinline__ float ex2f(float x) {
    float y; asm("ex2.approx.f32 %0, %1;" : "=f"(y) : "f"(x)); return y;
}
__device__ __forceinline__ float lg2f(float x) {
    float y; asm("lg2.approx.f32 %0, %1;" : "=f"(y) : "f"(x)); return y;
}

__global__ void __launch_bounds__(TPB)
retina_fused(const float* __restrict__ t_xywh,
             const float* __restrict__ logits,
             const float* __restrict__ gtb,
             const int*   __restrict__ gtc,
             float* __restrict__ out)
{
    __shared__ float  s_ox[NG_*64];   // [g][w]  x-overlap, clamped >=0   (8KB)
    __shared__ float  s_oy[NG_*8];    // [g][h8] y-overlap, clamped >=0   (1KB)
    __shared__ float2 s_c  [NG_];     // (Cg/3, 2Cg/7) pos/neg thresholds
    __shared__ float  s_Cg [NG_];     // areaA + area_g (repair path)
    __shared__ float4 s_tlbr[NG_];
    __shared__ float4 s_box [NG_];
    __shared__ int    s_cat [NG_];
    __shared__ float  s_penf[TPB];
    __shared__ float  s_red[3][16];
    __shared__ float  s_fin[24];
    __shared__ unsigned int s_last;

    const int bid = blockIdx.x;
    const int b   = bid / BPI;
    const int blk = bid % BPI;
    const int tid = threadIdx.x;

    const int n0 = blk * TPB;           // first anchor of block; a const, 8 h-rows
    const int a  = n0 >> 12;
    const int h0 = (n0 >> 6) & 63;
    const float aw = c_aw[a], ah = c_ah[a];
    const float areaA = aw * ah;

    if (tid < NG_) {
        float4 g = ((const float4*)gtb)[b*NG_ + tid];
        float hw = 0.5f*g.z, hh = 0.5f*g.w;
        s_tlbr[tid] = make_float4(g.x - hw, g.y - hh, g.x + hw, g.y + hh);
        s_box [tid] = g;
        s_cat [tid] = gtc[b*NG_ + tid];
        float Cg = areaA + g.z * g.w;
        s_c [tid] = make_float2(Cg * (1.0f/3.0f), Cg * (2.0f/7.0f));
        s_Cg[tid] = Cg;
    }
    __syncthreads();

    // ---- build overlap tables ----
    {
        const float kl = 4.0f - 0.5f*aw;       // x: left edge = w*8 + kl
        #pragma unroll
        for (int i = 0; i < (NG_*64)/TPB; ++i) {   // 4 entries/thread
            int idx = tid + i*TPB;
            int g = idx >> 6, w = idx & 63;
            float wl = fmaf((float)w, 8.0f, kl);
            float wr = wl + aw;
            s_ox[idx] = fmaxf(fminf(wr, s_tlbr[g].z) - fmaxf(wl, s_tlbr[g].x), 0.0f);
        }
        if (tid < NG_*8) {
            int g = tid >> 3, hh = tid & 7;
            float yl = fmaf((float)(h0 + hh), 8.0f, 4.0f - 0.5f*ah);
            float yr = yl + ah;
            s_oy[tid] = fmaxf(fminf(yr, s_tlbr[g].w) - fmaxf(yl, s_tlbr[g].y), 0.0f);
        }
    }
    __syncthreads();

    // ---- phase 1: pos/neg via running maxima (no argmax, no union) ----
    const int h8 = tid >> 6;           // 0..7
    const int w  = tid & 63;
    const float* oxp = s_ox + w;       // stride 64 per g
    const float* oyp = s_oy + h8;      // stride 8  per g (warp-broadcast)

    float m1 = -1e30f, m2 = -1e30f;
    #pragma unroll 8
    for (int g = 0; g < NG_; ++g) {
        float ox = oxp[g << 6];
        float oy = oyp[g << 3];
        float2 c = s_c[g];
        m1 = fmaxf(m1, fmaf(ox, oy, -c.x));   // I - Cg/3   (>0 <=> IoU>0.5)
        m2 = fmaxf(m2, fmaf(ox, oy, -c.y));   // I - 2Cg/7  (<0 <=> IoU<0.4)
    }
    const bool pos = m1 > 0.0f;
    const bool neg = m2 < 0.0f;

    // ---- rare repair path: argmax + regression target for pos anchors ----
    float l_xywh = 0.0f;
    float sub    = 0.0f;     // one-hot -x[tc] term
    if (__any_sync(0xFFFFFFFFu, pos)) {
        float bI = 0.0f, bU = 1.0f; int bG = 0;
        #pragma unroll 4
        for (int g = 0; g < NG_; ++g) {
            float I = oxp[g << 6] * oyp[g << 3];
            float U = s_Cg[g] - I;
            if (I * bU > bI * U) { bI = I; bU = U; bG = g; }
        }
        if (pos) {
            const int n = n0 + tid;
            const int h = h0 + h8;
            const float acx = ((float)w + 0.5f) * 8.0f;
            const float acy = ((float)h + 0.5f) * 8.0f;
            float4 gbx = s_box[bG];
            float tx = (gbx.x - acx) / aw;
            float ty = (gbx.y - acy) / ah;
            float tw = __logf(gbx.z / aw + 1e-8f);
            float th = __logf(gbx.w / ah + 1e-8f);
            float4 t = ((const float4*)t_xywh)[ (size_t)((b*NA_ + a) << 12) + (h << 6) + w ];
            float dx = t.x - tx, dy = t.y - ty, dw = t.z - tw, dh = t.w - th;
            l_xywh = dx*dx + dy*dy + dw*dw + dh*dh;
            sub = logits[(size_t)(b*NANCH + n)*NC_ + s_cat[bG]];
        }
    }

    s_penf[tid] = (pos | neg) ? 1.0f : 0.0f;
    __syncthreads();

    // ---- phase 2: coalesced BCE over 512 anchors x 80 classes ----
    // softplus(x) = relu(x) + log1p(e^-|x|);  sum relu = 0.5*(sum x + sum |x|)
    // (|.| is a free operand modifier -> all on fma pipe, alu pipe relieved).
    // 16 (1+y) factors batched per lg2 (product in [1,2^16], safe in f32).
    const float4* lp = (const float4*)logits + (size_t)(b*NANCH + n0)*(NC_/4);
    float acc_r = 0.0f, acc_l = 0.0f, p = 1.0f;
    #pragma unroll
    for (int k = 0; k < NITER; ++k) {
        const int idx4   = tid + k*TPB;
        const int anchor = idx4 / NITER;
        const float pen  = s_penf[anchor];
        float4 v = lp[idx4];
        float y0 = ex2f(-1.4426950408889634f * fabsf(v.x));
        float y1 = ex2f(-1.4426950408889634f * fabsf(v.y));
        float y2 = ex2f(-1.4426950408889634f * fabsf(v.z));
        float y3 = ex2f(-1.4426950408889634f * fabsf(v.w));
        float q = 1.0f + y0;
        q = __fmaf_rn(q, y1, q);
        q = __fmaf_rn(q, y2, q);
        q = __fmaf_rn(q, y3, q);
        p *= __fmaf_rn(pen, q - 1.0f, 1.0f);       // pen? p*q : p, predicate-free
        float sx = (v.x + v.y) + (v.z + v.w);
        float sa = (fabsf(v.x) + fabsf(v.y)) + (fabsf(v.z) + fabsf(v.w));
        acc_r = __fmaf_rn(pen, sx + sa, acc_r);
        if ((k & 3) == 3) { acc_l += lg2f(p); p = 1.0f; }
    }
    float acc_cls = __fmaf_rn(0.5f, acc_r, -sub) + 0.6931471805599453f * acc_l;

    // ---- block reduction of (cls, xywh, npos): 16 warps ----
    float v0 = acc_cls, v1 = l_xywh, v2 = pos ? 1.0f : 0.0f;
    #pragma unroll
    for (int o = 16; o; o >>= 1) {
        v0 += __shfl_down_sync(0xFFFFFFFFu, v0, o);
        v1 += __shfl_down_sync(0xFFFFFFFFu, v1, o);
        v2 += __shfl_down_sync(0xFFFFFFFFu, v2, o);
    }
    const int lane = tid & 31, wrp = tid >> 5;
    if (lane == 0) { s_red[0][wrp] = v0; s_red[1][wrp] = v1; s_red[2][wrp] = v2; }
    __syncthreads();
    if (wrp == 0 && lane < 16) {
        v0 = s_red[0][lane]; v1 = s_red[1][lane]; v2 = s_red[2][lane];
        #pragma unroll
        for (int o = 8; o; o >>= 1) {
            v0 += __shfl_down_sync(0x0000FFFFu, v0, o);
            v1 += __shfl_down_sync(0x0000FFFFu, v1, o);
            v2 += __shfl_down_sync(0x0000FFFFu, v2, o);
        }
        if (lane == 0) { g_cls[bid] = v0; g_xywh[bid] = v1; g_npos[bid] = v2; }
    }
    __syncthreads();

    // ---- last-block-done: final deterministic reduction, no 2nd launch ----
    if (tid == 0) {
        __threadfence();
        s_last = (atomicAdd(&g_count, 1u) == NBLK - 1u);
    }
    __syncthreads();
    if (!s_last) return;
    __threadfence();

    // global xywh sum over all 576 partials (fixed order -> deterministic)
    float sx = 0.0f;
    for (int i = tid; i < NBLK; i += TPB) sx += __ldcg(&g_xywh[i]);
    #pragma unroll
    for (int o = 16; o; o >>= 1) sx += __shfl_down_sync(0xFFFFFFFFu, sx, o);
    if (lane == 0) s_fin[wrp] = sx;

    // per-image cls sum / (npos+1): warp `wrp` (<8) handles image `wrp`
    if (wrp < 8) {
        float sc = 0.0f, sp = 0.0f;
        for (int i = lane; i < BPI; i += 32) {
            sc += __ldcg(&g_cls [wrp*BPI + i]);
            sp += __ldcg(&g_npos[wrp*BPI + i]);
        }
        #pragma unroll
        for (int o = 16; o; o >>= 1) {
            sc += __shfl_down_sync(0xFFFFFFFFu, sc, o);
            sp += __shfl_down_sync(0xFFFFFFFFu, sp, o);
        }
        if (lane == 0) s_fin[16 + wrp] = sc / (sp + 1.0f);
    }
    __syncthreads();

    if (tid == 0) {
        float tot = 0.0f;
        #pragma unroll
        for (int i = 0; i < 24; ++i) tot += s_fin[i];
        out[0] = tot * (1.0f / (float)B_);
        g_count = 0;   // reset for next graph replay
    }
}

extern "C" void kernel_launch(void* const* d_in, const int* in_sizes, int n_in,
                              void* d_out, int out_size)
{
    const float* t_xywh = (const float*)d_in[0];
    const float* logits = (const float*)d_in[1];
    const float* gtb    = (const float*)d_in[2];
    const int*   gtc    = (const int*)  d_in[3];
    (void)in_sizes; (void)n_in; (void)out_size;

    retina_fused<<<NBLK, TPB>>>(t_xywh, logits, gtb, gtc, (float*)d_out);
}